// round 2
// baseline (speedup 1.0000x reference)
#include <cuda_runtime.h>
#include <math.h>

// Problem constants
#define B_    16
#define C_    64
#define H_    224
#define W_    224
#define HW_   (H_ * W_)          // 50176
#define CHW_  (C_ * HW_)         // 3211264
#define HW4_  (HW_ / 4)          // 12544
#define CHW4_ (CHW_ / 4)         // 802816

#define CHUNK_B 8                // 8 batches = 102.8 MB of x, fits in 126 MB L2

// Scratch (device globals — no allocation allowed)
__device__ float g_avg[B_ * HW_];   // 3.2 MB
__device__ float g_max[B_ * HW_];   // 3.2 MB
__device__ float g_gate[B_ * HW_];  // 3.2 MB (post-sigmoid)

// ---------------------------------------------------------------------------
// Kernel 1: channel-wise mean + max reduce over one batch-chunk.
// One thread = 4 consecutive w positions; 64 channel-strided LDG.128.
// Side effect: streams the chunk of x through L2 (it fits → stays resident).
// ---------------------------------------------------------------------------
__global__ void reduce_kernel(const float* __restrict__ x, int b0) {
    int idx = blockIdx.x * blockDim.x + threadIdx.x;   // float4 idx in [0, CHUNK_B*HW4_)
    if (idx >= CHUNK_B * HW4_) return;
    int bl = idx / HW4_;
    int p  = idx - bl * HW4_;
    int b  = b0 + bl;

    const float4* x4 = (const float4*)x;
    long base = (long)b * CHW4_ + p;

    float4 s = make_float4(0.f, 0.f, 0.f, 0.f);
    float4 m = make_float4(-INFINITY, -INFINITY, -INFINITY, -INFINITY);

#pragma unroll 8
    for (int c = 0; c < C_; c++) {
        float4 v = x4[base + (long)c * HW4_];
        s.x += v.x; s.y += v.y; s.z += v.z; s.w += v.w;
        m.x = fmaxf(m.x, v.x); m.y = fmaxf(m.y, v.y);
        m.z = fmaxf(m.z, v.z); m.w = fmaxf(m.w, v.w);
    }
    const float inv = 1.0f / (float)C_;
    s.x *= inv; s.y *= inv; s.z *= inv; s.w *= inv;

    ((float4*)g_avg)[b * HW4_ + p] = s;
    ((float4*)g_max)[b * HW4_ + p] = m;
}

// ---------------------------------------------------------------------------
// Kernel 2: 7x7 conv (2ch -> 1ch, pad 3) + bias + sigmoid -> gate.
// Block (28,8); each thread computes 4 outputs along w (tile 112x8).
// Smem halo tile 2 x 14 x 118 (row stride padded to 120 for LDS.128 align).
// ---------------------------------------------------------------------------
#define CTW  112          // outputs per tile in w
#define CTH  8            // outputs per tile in h
#define HTW  118          // CTW + 6
#define HTH  14           // CTH + 6
#define HTWP 120          // padded row stride (multiple of 4 -> 16B aligned rows)

__global__ void conv_sigmoid_kernel(const float* __restrict__ conv_w,
                                    const float* __restrict__ conv_b, int b0) {
    __shared__ float s_tile[2 * HTH * HTWP];   // 13.4 KB
    __shared__ float s_w[98];

    int tx  = threadIdx.x;              // 0..27
    int ty  = threadIdx.y;              // 0..7
    int tid = ty * 28 + tx;             // 0..223

    int w0 = blockIdx.x * CTW;          // 2 blocks
    int h0 = blockIdx.y * CTH;          // 28 blocks
    int b  = b0 + blockIdx.z;           // CHUNK_B

    if (tid < 98) s_w[tid] = conv_w[tid];

    // cooperative halo load: 2 * 14 * 118 = 3304 elements
    const float* srcA = g_avg + b * HW_;
    const float* srcM = g_max + b * HW_;
    for (int i = tid; i < 2 * HTH * HTW; i += 224) {
        int ch = i / (HTH * HTW);
        int r  = (i - ch * HTH * HTW) / HTW;
        int cc = i - ch * HTH * HTW - r * HTW;
        int gh = h0 + r - 3;
        int gw = w0 + cc - 3;
        float v = 0.f;
        if (gh >= 0 && gh < H_ && gw >= 0 && gw < W_)
            v = (ch == 0 ? srcA : srcM)[gh * W_ + gw];
        s_tile[ch * HTH * HTWP + r * HTWP + cc] = v;
    }
    __syncthreads();

    float acc0 = conv_b[0], acc1 = acc0, acc2 = acc0, acc3 = acc0;

#pragma unroll
    for (int ch = 0; ch < 2; ch++) {
#pragma unroll
        for (int kh = 0; kh < 7; kh++) {
            const float* row = s_tile + ch * HTH * HTWP + (ty + kh) * HTWP;
            // 10 contiguous floats starting at 4*tx: two LDS.128 + two LDS
            float4 v0 = *(const float4*)(row + 4 * tx);
            float4 v1 = *(const float4*)(row + 4 * tx + 4);
            float  e0 = row[4 * tx + 8];
            float  e1 = row[4 * tx + 9];
            float r_[10] = { v0.x, v0.y, v0.z, v0.w,
                             v1.x, v1.y, v1.z, v1.w, e0, e1 };
            const float* wk = s_w + ch * 49 + kh * 7;
#pragma unroll
            for (int kw = 0; kw < 7; kw++) {
                float wv = wk[kw];
                acc0 = fmaf(r_[kw + 0], wv, acc0);
                acc1 = fmaf(r_[kw + 1], wv, acc1);
                acc2 = fmaf(r_[kw + 2], wv, acc2);
                acc3 = fmaf(r_[kw + 3], wv, acc3);
            }
        }
    }

    float4 gate;
    gate.x = 1.0f / (1.0f + __expf(-acc0));
    gate.y = 1.0f / (1.0f + __expf(-acc1));
    gate.z = 1.0f / (1.0f + __expf(-acc2));
    gate.w = 1.0f / (1.0f + __expf(-acc3));

    int out_idx = b * HW_ + (h0 + ty) * W_ + w0 + 4 * tx;   // 16B aligned
    *(float4*)(g_gate + out_idx) = gate;
}

// ---------------------------------------------------------------------------
// Kernel 3: out = x * gate for one batch-chunk.
// x read should mostly hit L2 (chunk resident from kernel 1).
// out stored with __stcs (evict-first) to avoid thrashing the resident chunk.
// ---------------------------------------------------------------------------
__global__ void gate_mul_kernel(const float* __restrict__ x,
                                float* __restrict__ out, int b0) {
    int idx4 = blockIdx.x * blockDim.x + threadIdx.x;  // [0, CHUNK_B*CHW4_)
    if (idx4 >= CHUNK_B * CHW4_) return;

    int bl  = idx4 / CHW4_;
    int r   = idx4 - bl * CHW4_;
    int hw4 = r % HW4_;
    int b   = b0 + bl;

    long g_idx = (long)b * CHW4_ + r;
    float4 g = ((const float4*)g_gate)[b * HW4_ + hw4];
    float4 v = ((const float4*)x)[g_idx];
    v.x *= g.x; v.y *= g.y; v.z *= g.z; v.w *= g.w;
    __stcs(((float4*)out) + g_idx, v);
}

// ---------------------------------------------------------------------------
extern "C" void kernel_launch(void* const* d_in, const int* in_sizes, int n_in,
                              void* d_out, int out_size) {
    const float* x      = (const float*)d_in[0];
    const float* conv_w = (const float*)d_in[1];
    const float* conv_b = (const float*)d_in[2];
    float* out = (float*)d_out;

    for (int c = 0; c < B_ / CHUNK_B; c++) {
        int b0 = c * CHUNK_B;

        // K1: reduce over channels (streams chunk of x into L2)
        {
            int n = CHUNK_B * HW4_;          // 100352 threads
            reduce_kernel<<<(n + 255) / 256, 256>>>(x, b0);
        }
        // K2: conv + sigmoid -> gate
        {
            dim3 blk(28, 8);
            dim3 grd(W_ / CTW, H_ / CTH, CHUNK_B);  // 2 x 28 x 8
            conv_sigmoid_kernel<<<grd, blk>>>(conv_w, conv_b, b0);
        }
        // K3: broadcast multiply (x from L2, streaming stores)
        {
            int n = CHUNK_B * CHW4_;         // 6,422,528
            gate_mul_kernel<<<(n + 255) / 256, 256>>>(x, out, b0);
        }
    }
}

// round 3
// speedup vs baseline: 1.1702x; 1.1702x over previous
#include <cuda_runtime.h>
#include <math.h>

// Problem constants
#define B_    16
#define C_    64
#define H_    224
#define W_    224
#define HW_   (H_ * W_)          // 50176
#define CHW_  (C_ * HW_)         // 3211264
#define HW4_  (HW_ / 4)          // 12544
#define CHW4_ (CHW_ / 4)         // 802816

// Scratch (device globals — no allocation allowed)
__device__ float g_avg[B_ * HW_];   // 3.2 MB
__device__ float g_max[B_ * HW_];   // 3.2 MB

// ---------------------------------------------------------------------------
// Kernel 1: channel-wise mean + max reduce (R1 version — hits 79.5% DRAM).
// One thread = 4 consecutive w positions; 64 channel-strided LDG.128.
// ---------------------------------------------------------------------------
__global__ void reduce_kernel(const float* __restrict__ x) {
    int idx = blockIdx.x * blockDim.x + threadIdx.x;   // float4 idx in [0, B_*HW4_)
    if (idx >= B_ * HW4_) return;
    int b = idx / HW4_;
    int p = idx - b * HW4_;

    const float4* x4 = (const float4*)x;
    long base = (long)b * CHW4_ + p;

    float4 s = make_float4(0.f, 0.f, 0.f, 0.f);
    float4 m = make_float4(-INFINITY, -INFINITY, -INFINITY, -INFINITY);

#pragma unroll 8
    for (int c = 0; c < C_; c++) {
        float4 v = x4[base + (long)c * HW4_];
        s.x += v.x; s.y += v.y; s.z += v.z; s.w += v.w;
        m.x = fmaxf(m.x, v.x); m.y = fmaxf(m.y, v.y);
        m.z = fmaxf(m.z, v.z); m.w = fmaxf(m.w, v.w);
    }
    const float inv = 1.0f / (float)C_;
    s.x *= inv; s.y *= inv; s.z *= inv; s.w *= inv;

    ((float4*)g_avg)[idx] = s;
    ((float4*)g_max)[idx] = m;
}

// ---------------------------------------------------------------------------
// Kernel 2 (fused): conv7x7 + sigmoid -> gate (registers) -> out = x * gate.
// One CTA = one (batch, 4-row band). 224 threads; thread t owns the float4 at
// (row = t/56, w = 4*(t%56)). Phase 1: smem halo tile of feat, compute 4 gates
// into a float4 register. Phase 2: 64 channel iterations of LDG.128 -> STG.128.
// Gate compute amortized 64x; no intermediate gate tensor, no third kernel.
// ---------------------------------------------------------------------------
#define BAND  4                 // output rows per CTA
#define HR    10                // BAND + 6 halo rows
#define HC    230               // 224 + 6 halo cols
#define HCP   232               // padded row stride (232*4B = 928B, 16B-aligned)

__global__ void __launch_bounds__(224) fused_gate_mul_kernel(
        const float* __restrict__ x,
        const float* __restrict__ conv_w,
        const float* __restrict__ conv_b,
        float* __restrict__ out) {
    __shared__ float s_feat[2 * HR * HCP];   // 18.6 KB
    __shared__ float s_w[98];

    int t  = threadIdx.x;            // 0..223
    int h0 = blockIdx.x * BAND;      // 56 bands
    int b  = blockIdx.y;             // 16 batches

    if (t < 98) s_w[t] = conv_w[t];

    // Halo load: 2 ch x 10 rows x 230 cols = 4600 elements from L2-resident feat
    const float* srcA = g_avg + b * HW_;
    const float* srcM = g_max + b * HW_;
    for (int i = t; i < 2 * HR * HC; i += 224) {
        int ch = i / (HR * HC);
        int r  = (i - ch * HR * HC) / HC;
        int cc = i - ch * HR * HC - r * HC;
        int gh = h0 + r - 3;
        int gw = cc - 3;
        float v = 0.f;
        if (gh >= 0 && gh < H_ && gw >= 0 && gw < W_)
            v = (ch == 0 ? srcA : srcM)[gh * W_ + gw];
        s_feat[ch * HR * HCP + r * HCP + cc] = v;
    }
    __syncthreads();

    int row = t / 56;                // 0..3
    int w4  = t - row * 56;          // 0..55  (w = 4*w4)

    // Phase 1: 7x7 conv over 2 channels for the thread's 4 outputs
    float acc0 = conv_b[0], acc1 = acc0, acc2 = acc0, acc3 = acc0;
#pragma unroll
    for (int ch = 0; ch < 2; ch++) {
#pragma unroll
        for (int kh = 0; kh < 7; kh++) {
            const float* rp = s_feat + ch * HR * HCP + (row + kh) * HCP + 4 * w4;
            float4 v0 = *(const float4*)(rp);       // LDS.128 (16B-aligned)
            float4 v1 = *(const float4*)(rp + 4);
            float  e0 = rp[8];
            float  e1 = rp[9];
            float r_[10] = { v0.x, v0.y, v0.z, v0.w,
                             v1.x, v1.y, v1.z, v1.w, e0, e1 };
            const float* wk = s_w + ch * 49 + kh * 7;
#pragma unroll
            for (int kw = 0; kw < 7; kw++) {
                float wv = wk[kw];
                acc0 = fmaf(r_[kw + 0], wv, acc0);
                acc1 = fmaf(r_[kw + 1], wv, acc1);
                acc2 = fmaf(r_[kw + 2], wv, acc2);
                acc3 = fmaf(r_[kw + 3], wv, acc3);
            }
        }
    }

    float4 g;
    g.x = 1.0f / (1.0f + __expf(-acc0));
    g.y = 1.0f / (1.0f + __expf(-acc1));
    g.z = 1.0f / (1.0f + __expf(-acc2));
    g.w = 1.0f / (1.0f + __expf(-acc3));

    // Phase 2: multiply across all 64 channels (channel-strided LDG/STG.128)
    long base4 = (long)b * CHW4_ + ((h0 + row) * W_ + 4 * w4) / 4;
    const float4* x4 = (const float4*)x;
    float4* o4 = (float4*)out;

#pragma unroll 8
    for (int c = 0; c < C_; c++) {
        long idx = base4 + (long)c * HW4_;
        float4 v = x4[idx];
        v.x *= g.x; v.y *= g.y; v.z *= g.z; v.w *= g.w;
        __stcs(o4 + idx, v);
    }
}

// ---------------------------------------------------------------------------
extern "C" void kernel_launch(void* const* d_in, const int* in_sizes, int n_in,
                              void* d_out, int out_size) {
    const float* x      = (const float*)d_in[0];
    const float* conv_w = (const float*)d_in[1];
    const float* conv_b = (const float*)d_in[2];
    float* out = (float*)d_out;

    // K1: channel reduce over full tensor
    {
        int n = B_ * HW4_;                   // 200704 threads
        reduce_kernel<<<(n + 255) / 256, 256>>>(x);
    }
    // K2: fused conv + sigmoid + broadcast multiply
    {
        dim3 grd(H_ / BAND, B_);             // 56 x 16 = 896 CTAs
        fused_gate_mul_kernel<<<grd, 224>>>(x, conv_w, conv_b, out);
    }
}